// round 14
// baseline (speedup 1.0000x reference)
#include <cuda_runtime.h>
#include <cuda_fp16.h>

#define NPOOL 100000
#define NUN   200000
#define NEDGE 1200000
#define CH    64
#define EPSV  1e-5f

#define SCAN_BLK   512
#define SCAN_ITEMS 8
#define SCAN_TILE  (SCAN_BLK * SCAN_ITEMS)                 // 4096
#define NSCAN      ((NUN + SCAN_TILE - 1) / SCAN_TILE)     // 49
#define GROWS      128                                     // gemm rows per block
#define NB1        ((NPOOL + GROWS - 1) / GROWS)           // 782 gemm blocks
#define GEMM_SMEM  ((4096 + GROWS * 68) * 4)               // 51200 bytes
#define STATS_GRID 296

// ---------------- scratch ----------------
__device__ __half2 g_Pp [NPOOL * 32];     // x @ W1 (fp16, 128B/row)
__device__ __half2 g_HWp[NPOOL * 32];     // relu(bn1(...)) @ Wg (fp16, 128B/row)
__device__ __half2 g_ACCh[NUN * 32];      // GCN result pre-BN2 (fp16, 128B/row)
__device__ int     g_indeg[NUN];
__device__ float   g_dis[NUN];
__device__ int     g_cnt[NPOOL];
__device__ int     g_off[NUN + 1];
__device__ int     g_cur[NUN];
__device__ int2    g_ent[NEDGE];          // {cluster[src], bits(dis[src])} by dst
__device__ int     g_bsum[NSCAN], g_bpre[NSCAN];
__device__ float   g_p1s[64 * NB1];       // BN1 per-block partials
__device__ float   g_p1q[64 * NB1];
__device__ double  g_s2[CH], g_q2[CH];
__device__ float   g_scale1[CH], g_shift1[CH], g_scale2[CH], g_shift2[CH];

// ---------------- split init: chain A / chain B heads ----------------
__global__ void k_initA() {
    int i = blockIdx.x * blockDim.x + threadIdx.x;
    if (i < NUN) g_indeg[i] = 0;
}
__global__ void k_initB() {
    int i = blockIdx.x * blockDim.x + threadIdx.x;
    if (i < NPOOL) g_cnt[i] = 0;
    if (i < CH) { g_s2[i] = 0.0; g_q2[i] = 0.0; }
}

// ---------------- in-degree (dst) ----------------
__global__ void k_deg(const int* __restrict__ dst) {
    int i = blockIdx.x * blockDim.x + threadIdx.x;
    if (i < NEDGE) atomicAdd(&g_indeg[dst[i]], 1);
}

// ---------------- cluster histogram ----------------
__global__ void k_cnt(const int* __restrict__ cluster) {
    int i = blockIdx.x * blockDim.x + threadIdx.x;
    if (i < NUN) atomicAdd(&g_cnt[cluster[i]], 1);
}

// ---------------- scan A: per-block sums of indeg; also compute dis ----------------
__global__ __launch_bounds__(SCAN_BLK) void k_scanA() {
    __shared__ int sh[SCAN_BLK];
    int t = threadIdx.x;
    int base = blockIdx.x * SCAN_TILE + t * SCAN_ITEMS;
    int s = 0;
#pragma unroll
    for (int i = 0; i < SCAN_ITEMS; i++) {
        int idx = base + i;
        if (idx < NUN) {
            int dg = g_indeg[idx];
            s += dg;
            g_dis[idx] = rsqrtf((float)dg + 1.0f);
        }
    }
    sh[t] = s;
    __syncthreads();
    for (int off = SCAN_BLK / 2; off > 0; off >>= 1) {
        if (t < off) sh[t] += sh[t + off];
        __syncthreads();
    }
    if (t == 0) g_bsum[blockIdx.x] = sh[0];
}

// ---------------- GEMM1: Pp(fp16) = x @ W1 ; fused BN1 partials ----------------
// 256 threads, 128 rows/block, dynamic smem, forced 4 blocks/SM (regs <= 64).
__global__ __launch_bounds__(256, 4) void k_gemm1(const float* __restrict__ x,
                                                  const float* __restrict__ W,
                                                  const float* __restrict__ score,
                                                  const float* __restrict__ b1) {
    extern __shared__ float smem[];
    float* Ws = smem;              // 64*64
    float* Xs = smem + 4096;       // 128*68
    int t = threadIdx.x;
    for (int i = t; i < 1024; i += 256)
        ((float4*)Ws)[i] = ((const float4*)W)[i];
    int row0 = blockIdx.x * GROWS;
#pragma unroll
    for (int j = 0; j < 8; j++) {
        int i = t + j * 256;
        int r = i >> 4, c4 = i & 15;
        int row = row0 + r;
        float4 v = make_float4(0.f, 0.f, 0.f, 0.f);
        if (row < NPOOL) v = ((const float4*)(x + (size_t)row * CH))[c4];
        *((float4*)(Xs + r * 68 + c4 * 4)) = v;
    }
    __syncthreads();
    int cg = t & 7, rg = t >> 3;   // rg 0..31
    float acc[4][8];
#pragma unroll
    for (int r = 0; r < 4; r++)
#pragma unroll
        for (int c = 0; c < 8; c++) acc[r][c] = 0.f;
    for (int k = 0; k < 64; k++) {
        float4 w0 = *((float4*)(Ws + k * 64 + cg * 8));
        float4 w1 = *((float4*)(Ws + k * 64 + cg * 8 + 4));
#pragma unroll
        for (int r = 0; r < 4; r++) {
            float xv = Xs[(rg + 32 * r) * 68 + k];
            acc[r][0] = fmaf(xv, w0.x, acc[r][0]);
            acc[r][1] = fmaf(xv, w0.y, acc[r][1]);
            acc[r][2] = fmaf(xv, w0.z, acc[r][2]);
            acc[r][3] = fmaf(xv, w0.w, acc[r][3]);
            acc[r][4] = fmaf(xv, w1.x, acc[r][4]);
            acc[r][5] = fmaf(xv, w1.y, acc[r][5]);
            acc[r][6] = fmaf(xv, w1.z, acc[r][6]);
            acc[r][7] = fmaf(xv, w1.w, acc[r][7]);
        }
    }
#pragma unroll
    for (int r = 0; r < 4; r++) {
        int row = row0 + rg + 32 * r;
        if (row < NPOOL) {
            __half2 h0 = __floats2half2_rn(acc[r][0], acc[r][1]);
            __half2 h1 = __floats2half2_rn(acc[r][2], acc[r][3]);
            __half2 h2 = __floats2half2_rn(acc[r][4], acc[r][5]);
            __half2 h3 = __floats2half2_rn(acc[r][6], acc[r][7]);
            uint4 u;
            u.x = *reinterpret_cast<unsigned*>(&h0);
            u.y = *reinterpret_cast<unsigned*>(&h1);
            u.z = *reinterpret_cast<unsigned*>(&h2);
            u.w = *reinterpret_cast<unsigned*>(&h3);
            *((uint4*)(g_Pp + (size_t)row * 32 + cg * 4)) = u;
        }
    }
    // ---- fused BN1 partials (exact fp32 registers) ----
    float4 b1a = ((const float4*)b1)[cg * 2];
    float4 b1b = ((const float4*)b1)[cg * 2 + 1];
    float bcol[8] = {b1a.x, b1a.y, b1a.z, b1a.w, b1b.x, b1b.y, b1b.z, b1b.w};
    float s8[8], q8[8];
#pragma unroll
    for (int c = 0; c < 8; c++) { s8[c] = 0.f; q8[c] = 0.f; }
#pragma unroll
    for (int r = 0; r < 4; r++) {
        int row = row0 + rg + 32 * r;
        if (row < NPOOL) {
            float fw = (float)g_cnt[row];
            if (fw > 0.f) {
                float inv = 1.0f / score[row];
#pragma unroll
                for (int c = 0; c < 8; c++) {
                    float v = fmaf(acc[r][c], inv, bcol[c]);
                    s8[c] = fmaf(fw, v, s8[c]);
                    q8[c] = fmaf(fw * v, v, q8[c]);
                }
            }
        }
    }
    __syncthreads();                 // done reading Xs; reuse it
    float* Ss = Xs;                  // [32][64]
    float* Qs = Xs + 2048;           // [32][64]
#pragma unroll
    for (int c = 0; c < 8; c++) {
        Ss[rg * 64 + cg * 8 + c] = s8[c];
        Qs[rg * 64 + cg * 8 + c] = q8[c];
    }
    __syncthreads();
    if (t < 128) {
        int c = t & 63;
        const float* base = (t < 64) ? Ss : Qs;
        float s = 0.f;
#pragma unroll
        for (int i = 0; i < 32; i++) s += base[i * 64 + c];
        if (t < 64) g_p1s[c * NB1 + blockIdx.x] = s;
        else        g_p1q[c * NB1 + blockIdx.x] = s;
    }
}

// ---------------- BN1 reduce + finalize ----------------
__global__ __launch_bounds__(1024) void k_bn1(const float* __restrict__ g1,
                                              const float* __restrict__ be1) {
    int t = threadIdx.x;
    int wid = t >> 5, lane = t & 31;
#pragma unroll
    for (int ci = 0; ci < 2; ci++) {
        int c = wid * 2 + ci;
        double s = 0.0, q = 0.0;
        for (int i = lane; i < NB1; i += 32) {
            s += (double)g_p1s[c * NB1 + i];
            q += (double)g_p1q[c * NB1 + i];
        }
#pragma unroll
        for (int o = 16; o > 0; o >>= 1) {
            s += __shfl_down_sync(0xFFFFFFFFu, s, o);
            q += __shfl_down_sync(0xFFFFFFFFu, q, o);
        }
        if (lane == 0) {
            double invN = 1.0 / (double)NUN;
            float mu = (float)(s * invN);
            float var = (float)(q * invN) - mu * mu;
            if (var < 0.f) var = 0.f;
            float rs = rsqrtf(var + EPSV);
            float sc = g1[c] * rs;
            g_scale1[c] = sc;
            g_shift1[c] = be1[c] - mu * sc;
        }
    }
}

// ---------------- scan B ----------------
__global__ void k_scanB() {
    if (threadIdx.x == 0) {
        int run = 0;
        for (int b = 0; b < NSCAN; b++) { g_bpre[b] = run; run += g_bsum[b]; }
        g_off[NUN] = run;
    }
}

// ---------------- scan C ----------------
__global__ __launch_bounds__(SCAN_BLK) void k_scanC() {
    __shared__ int wsum[16];
    int t = threadIdx.x;
    int lane = t & 31, wid = t >> 5;
    int base = blockIdx.x * SCAN_TILE + t * SCAN_ITEMS;
    int v[SCAN_ITEMS];
    int s = 0;
#pragma unroll
    for (int i = 0; i < SCAN_ITEMS; i++) {
        int idx = base + i;
        v[i] = (idx < NUN) ? g_indeg[idx] : 0;
        s += v[i];
    }
    int incl = s;
#pragma unroll
    for (int off = 1; off < 32; off <<= 1) {
        int n = __shfl_up_sync(0xFFFFFFFFu, incl, off);
        if (lane >= off) incl += n;
    }
    if (lane == 31) wsum[wid] = incl;
    __syncthreads();
    if (wid == 0) {
        int x = (lane < 16) ? wsum[lane] : 0;
        int xi = x;
#pragma unroll
        for (int off = 1; off < 32; off <<= 1) {
            int n = __shfl_up_sync(0xFFFFFFFFu, xi, off);
            if (lane >= off) xi += n;
        }
        if (lane < 16) wsum[lane] = xi - x;
    }
    __syncthreads();
    int run = g_bpre[blockIdx.x] + wsum[wid] + (incl - s);
#pragma unroll
    for (int i = 0; i < SCAN_ITEMS; i++) {
        int idx = base + i;
        if (idx < NUN) { g_off[idx] = run; g_cur[idx] = run; run += v[i]; }
    }
}

// ---------------- fill ----------------
__global__ void k_fill(const int* __restrict__ src, const int* __restrict__ dst,
                       const int* __restrict__ cluster) {
    int e = blockIdx.x * blockDim.x + threadIdx.x;
    if (e < NEDGE) {
        int s = src[e], d = dst[e];
        int pos = atomicAdd(&g_cur[d], 1);
        g_ent[pos] = make_int2(cluster[s], __float_as_int(g_dis[s]));
    }
}

// ---------------- GEMM2: HWp(fp16) = relu(bn1(Pp/score + b1)) @ Wg ----------------
__global__ __launch_bounds__(256, 4) void k_gemm2(const float* __restrict__ Wg,
                                                  const float* __restrict__ score,
                                                  const float* __restrict__ b1) {
    extern __shared__ float smem[];
    float* Ws = smem;
    float* Xs = smem + 4096;
    int t = threadIdx.x;
    for (int i = t; i < 1024; i += 256)
        ((float4*)Ws)[i] = ((const float4*)Wg)[i];
    int row0 = blockIdx.x * GROWS;
#pragma unroll
    for (int j = 0; j < 8; j++) {
        int i = t + j * 256;
        int r = i >> 4, c4 = i & 15;
        int row = row0 + r;
        float4 v = make_float4(0.f, 0.f, 0.f, 0.f);
        if (row < NPOOL) {
            float inv = 1.0f / score[row];
            uint2 u = *((const uint2*)(g_Pp + (size_t)row * 32 + c4 * 2));
            float2 pa = __half22float2(*reinterpret_cast<__half2*>(&u.x));
            float2 pb = __half22float2(*reinterpret_cast<__half2*>(&u.y));
            float4 a   = ((const float4*)g_scale1)[c4];
            float4 sh  = ((const float4*)g_shift1)[c4];
            float4 b1v = ((const float4*)b1)[c4];
            v.x = fmaxf(fmaf(pa.x * inv, a.x, fmaf(b1v.x, a.x, sh.x)), 0.f);
            v.y = fmaxf(fmaf(pa.y * inv, a.y, fmaf(b1v.y, a.y, sh.y)), 0.f);
            v.z = fmaxf(fmaf(pb.x * inv, a.z, fmaf(b1v.z, a.z, sh.z)), 0.f);
            v.w = fmaxf(fmaf(pb.y * inv, a.w, fmaf(b1v.w, a.w, sh.w)), 0.f);
        }
        *((float4*)(Xs + r * 68 + c4 * 4)) = v;
    }
    __syncthreads();
    int cg = t & 7, rg = t >> 3;
    float acc[4][8];
#pragma unroll
    for (int r = 0; r < 4; r++)
#pragma unroll
        for (int c = 0; c < 8; c++) acc[r][c] = 0.f;
    for (int k = 0; k < 64; k++) {
        float4 w0 = *((float4*)(Ws + k * 64 + cg * 8));
        float4 w1 = *((float4*)(Ws + k * 64 + cg * 8 + 4));
#pragma unroll
        for (int r = 0; r < 4; r++) {
            float xv = Xs[(rg + 32 * r) * 68 + k];
            acc[r][0] = fmaf(xv, w0.x, acc[r][0]);
            acc[r][1] = fmaf(xv, w0.y, acc[r][1]);
            acc[r][2] = fmaf(xv, w0.z, acc[r][2]);
            acc[r][3] = fmaf(xv, w0.w, acc[r][3]);
            acc[r][4] = fmaf(xv, w1.x, acc[r][4]);
            acc[r][5] = fmaf(xv, w1.y, acc[r][5]);
            acc[r][6] = fmaf(xv, w1.z, acc[r][6]);
            acc[r][7] = fmaf(xv, w1.w, acc[r][7]);
        }
    }
#pragma unroll
    for (int r = 0; r < 4; r++) {
        int row = row0 + rg + 32 * r;
        if (row < NPOOL) {
            __half2 h0 = __floats2half2_rn(acc[r][0], acc[r][1]);
            __half2 h1 = __floats2half2_rn(acc[r][2], acc[r][3]);
            __half2 h2 = __floats2half2_rn(acc[r][4], acc[r][5]);
            __half2 h3 = __floats2half2_rn(acc[r][6], acc[r][7]);
            uint4 u;
            u.x = *reinterpret_cast<unsigned*>(&h0);
            u.y = *reinterpret_cast<unsigned*>(&h1);
            u.z = *reinterpret_cast<unsigned*>(&h2);
            u.w = *reinterpret_cast<unsigned*>(&h3);
            *((uint4*)(g_HWp + (size_t)row * 32 + cg * 4)) = u;
        }
    }
}

// ---------------- gather: ACCh(fp16) = bg + HWp[cluster[d]]*dis^2 + in-edge sum ----------------
__global__ __launch_bounds__(256) void k_gather(const int* __restrict__ cluster,
                                                const float* __restrict__ bg) {
    int t = threadIdx.x;
    int rowIdx = t >> 4;
    int q = t & 15;
    int d = blockIdx.x * 16 + rowIdx;            // NUN % 16 == 0
    int   c0 = cluster[d];
    float dd = g_dis[d];
    float d2 = dd * dd;
    float4 a0 = ((const float4*)bg)[q];
    float4 a1 = make_float4(0.f, 0.f, 0.f, 0.f);
    float4 a2 = make_float4(0.f, 0.f, 0.f, 0.f);
    float4 a3 = make_float4(0.f, 0.f, 0.f, 0.f);
    {
        uint2 u = *((const uint2*)(g_HWp + (size_t)c0 * 32) + q);
        float2 fa = __half22float2(*reinterpret_cast<__half2*>(&u.x));
        float2 fb = __half22float2(*reinterpret_cast<__half2*>(&u.y));
        a0.x = fmaf(fa.x, d2, a0.x);
        a0.y = fmaf(fa.y, d2, a0.y);
        a0.z = fmaf(fb.x, d2, a0.z);
        a0.w = fmaf(fb.y, d2, a0.w);
    }
    int beg = g_off[d], end = g_off[d + 1];
    int j = beg;
    for (; j + 4 <= end; j += 4) {
        int2 e0 = g_ent[j];
        int2 e1 = g_ent[j + 1];
        int2 e2 = g_ent[j + 2];
        int2 e3 = g_ent[j + 3];
        float k0 = __int_as_float(e0.y) * dd;
        float k1 = __int_as_float(e1.y) * dd;
        float k2 = __int_as_float(e2.y) * dd;
        float k3 = __int_as_float(e3.y) * dd;
        uint2 u0 = *((const uint2*)(g_HWp + (size_t)e0.x * 32) + q);
        uint2 u1 = *((const uint2*)(g_HWp + (size_t)e1.x * 32) + q);
        uint2 u2 = *((const uint2*)(g_HWp + (size_t)e2.x * 32) + q);
        uint2 u3 = *((const uint2*)(g_HWp + (size_t)e3.x * 32) + q);
        float2 fa0 = __half22float2(*reinterpret_cast<__half2*>(&u0.x));
        float2 fb0 = __half22float2(*reinterpret_cast<__half2*>(&u0.y));
        float2 fa1 = __half22float2(*reinterpret_cast<__half2*>(&u1.x));
        float2 fb1 = __half22float2(*reinterpret_cast<__half2*>(&u1.y));
        float2 fa2 = __half22float2(*reinterpret_cast<__half2*>(&u2.x));
        float2 fb2 = __half22float2(*reinterpret_cast<__half2*>(&u2.y));
        float2 fa3 = __half22float2(*reinterpret_cast<__half2*>(&u3.x));
        float2 fb3 = __half22float2(*reinterpret_cast<__half2*>(&u3.y));
        a0.x = fmaf(fa0.x, k0, a0.x); a0.y = fmaf(fa0.y, k0, a0.y);
        a0.z = fmaf(fb0.x, k0, a0.z); a0.w = fmaf(fb0.y, k0, a0.w);
        a1.x = fmaf(fa1.x, k1, a1.x); a1.y = fmaf(fa1.y, k1, a1.y);
        a1.z = fmaf(fb1.x, k1, a1.z); a1.w = fmaf(fb1.y, k1, a1.w);
        a2.x = fmaf(fa2.x, k2, a2.x); a2.y = fmaf(fa2.y, k2, a2.y);
        a2.z = fmaf(fb2.x, k2, a2.z); a2.w = fmaf(fb2.y, k2, a2.w);
        a3.x = fmaf(fa3.x, k3, a3.x); a3.y = fmaf(fa3.y, k3, a3.y);
        a3.z = fmaf(fb3.x, k3, a3.z); a3.w = fmaf(fb3.y, k3, a3.w);
    }
    for (; j < end; j++) {
        int2 e0 = g_ent[j];
        float k0 = __int_as_float(e0.y) * dd;
        uint2 u0 = *((const uint2*)(g_HWp + (size_t)e0.x * 32) + q);
        float2 fa0 = __half22float2(*reinterpret_cast<__half2*>(&u0.x));
        float2 fb0 = __half22float2(*reinterpret_cast<__half2*>(&u0.y));
        a0.x = fmaf(fa0.x, k0, a0.x); a0.y = fmaf(fa0.y, k0, a0.y);
        a0.z = fmaf(fb0.x, k0, a0.z); a0.w = fmaf(fb0.y, k0, a0.w);
    }
    __half2 h0 = __floats2half2_rn((a0.x + a1.x) + (a2.x + a3.x),
                                   (a0.y + a1.y) + (a2.y + a3.y));
    __half2 h1 = __floats2half2_rn((a0.z + a1.z) + (a2.z + a3.z),
                                   (a0.w + a1.w) + (a2.w + a3.w));
    uint2 u;
    u.x = *reinterpret_cast<unsigned*>(&h0);
    u.y = *reinterpret_cast<unsigned*>(&h1);
    *((uint2*)(g_ACCh + (size_t)d * 32 + q * 2)) = u;
}

// ---------------- BN2 stats over fp16 ACC ----------------
__global__ __launch_bounds__(256) void k_stats2() {
    int t = threadIdx.x;
    float4 s4 = make_float4(0.f, 0.f, 0.f, 0.f);
    float4 q4 = make_float4(0.f, 0.f, 0.f, 0.f);
    const int total = NUN * 16;                 // uint2 units (4 cols each)
    int stride = gridDim.x * blockDim.x;
#pragma unroll 4
    for (int i = blockIdx.x * blockDim.x + t; i < total; i += stride) {
        uint2 u = ((const uint2*)g_ACCh)[i];
        float2 a = __half22float2(*reinterpret_cast<__half2*>(&u.x));
        float2 b = __half22float2(*reinterpret_cast<__half2*>(&u.y));
        s4.x += a.x; q4.x = fmaf(a.x, a.x, q4.x);
        s4.y += a.y; q4.y = fmaf(a.y, a.y, q4.y);
        s4.z += b.x; q4.z = fmaf(b.x, b.x, q4.z);
        s4.w += b.y; q4.w = fmaf(b.y, b.y, q4.w);
    }
    s4.x += __shfl_xor_sync(0xFFFFFFFFu, s4.x, 16);
    s4.y += __shfl_xor_sync(0xFFFFFFFFu, s4.y, 16);
    s4.z += __shfl_xor_sync(0xFFFFFFFFu, s4.z, 16);
    s4.w += __shfl_xor_sync(0xFFFFFFFFu, s4.w, 16);
    q4.x += __shfl_xor_sync(0xFFFFFFFFu, q4.x, 16);
    q4.y += __shfl_xor_sync(0xFFFFFFFFu, q4.y, 16);
    q4.z += __shfl_xor_sync(0xFFFFFFFFu, q4.z, 16);
    q4.w += __shfl_xor_sync(0xFFFFFFFFu, q4.w, 16);
    __shared__ float shs[8][64], shq[8][64];
    int wid = t >> 5, lane = t & 31;
    if (lane < 16) {
        shs[wid][lane * 4 + 0] = s4.x;
        shs[wid][lane * 4 + 1] = s4.y;
        shs[wid][lane * 4 + 2] = s4.z;
        shs[wid][lane * 4 + 3] = s4.w;
        shq[wid][lane * 4 + 0] = q4.x;
        shq[wid][lane * 4 + 1] = q4.y;
        shq[wid][lane * 4 + 2] = q4.z;
        shq[wid][lane * 4 + 3] = q4.w;
    }
    __syncthreads();
    if (t < 64) {
        float s = 0.f, qq = 0.f;
#pragma unroll
        for (int w = 0; w < 8; w++) { s += shs[w][t]; qq += shq[w][t]; }
        atomicAdd(&g_s2[t], (double)s);
        atomicAdd(&g_q2[t], (double)qq);
    }
}

// ---------------- finalize BN2 params ----------------
__global__ void k_meanvar2(const float* __restrict__ g, const float* __restrict__ b) {
    int t = threadIdx.x;
    if (t < CH) {
        double s = g_s2[t];
        double q = g_q2[t];
        double invN = 1.0 / (double)NUN;
        float mu = (float)(s * invN);
        float var = (float)(q * invN) - mu * mu;
        if (var < 0.f) var = 0.f;
        float rs = rsqrtf(var + EPSV);
        float sc = g[t] * rs;
        g_scale2[t] = sc;
        g_shift2[t] = b[t] - mu * sc;
    }
}

// ---------------- final: out = relu(bn2(ACCh)) ----------------
__global__ void k_final(float* __restrict__ out) {
    int i4 = blockIdx.x * blockDim.x + threadIdx.x;
    if (i4 < NUN * 16) {
        int c4 = i4 & 15;
        uint2 u = ((const uint2*)g_ACCh)[i4];
        float2 a = __half22float2(*reinterpret_cast<__half2*>(&u.x));
        float2 b = __half22float2(*reinterpret_cast<__half2*>(&u.y));
        float4 sc = ((const float4*)g_scale2)[c4];
        float4 sh = ((const float4*)g_shift2)[c4];
        float4 o;
        o.x = fmaxf(fmaf(a.x, sc.x, sh.x), 0.f);
        o.y = fmaxf(fmaf(a.y, sc.y, sh.y), 0.f);
        o.z = fmaxf(fmaf(b.x, sc.z, sh.z), 0.f);
        o.w = fmaxf(fmaf(b.y, sc.w, sh.w), 0.f);
        ((float4*)out)[i4] = o;
    }
}

// ---------------- optional tail ----------------
__global__ void k_tail(const int* __restrict__ ei, const int* __restrict__ batch,
                       float* __restrict__ out, int extra) {
    int i = blockIdx.x * blockDim.x + threadIdx.x;
    if (i < extra) {
        float v;
        if (i < 2 * NEDGE) v = (float)ei[i];
        else {
            int j = i - 2 * NEDGE;
            v = (j < NUN) ? (float)batch[j] : 0.f;
        }
        out[NUN * CH + i] = v;
    }
}

// ---------------- launch (multi-stream fork/join, no serial prologue) ----------------
extern "C" void kernel_launch(void* const* d_in, const int* in_sizes, int n_in,
                              void* d_out, int out_size) {
    const float* x       = (const float*)d_in[0];
    const int*   ei      = (const int*)  d_in[1];
    const int*   batch   = (const int*)  d_in[2];
    const int*   cluster = (const int*)  d_in[3];
    const float* score   = (const float*)d_in[4];
    const float* W1      = (const float*)d_in[5];
    const float* b1      = (const float*)d_in[6];
    const float* g1      = (const float*)d_in[7];
    const float* be1     = (const float*)d_in[8];
    const float* Wg      = (const float*)d_in[9];
    const float* bg      = (const float*)d_in[10];
    const float* g2      = (const float*)d_in[11];
    const float* be2     = (const float*)d_in[12];
    const int* srcA = ei;
    const int* dstA = ei + NEDGE;
    float* out = (float*)d_out;
    int extra = out_size - NUN * CH;

    static cudaStream_t sA = 0, sB = 0, sC = 0;
    static cudaEvent_t evRoot = 0, evA = 0, evB = 0, evC = 0;
    if (!sA) {
        cudaStreamCreateWithFlags(&sA, cudaStreamNonBlocking);
        cudaStreamCreateWithFlags(&sB, cudaStreamNonBlocking);
        cudaStreamCreateWithFlags(&sC, cudaStreamNonBlocking);
        cudaEventCreateWithFlags(&evRoot, cudaEventDisableTiming);
        cudaEventCreateWithFlags(&evA, cudaEventDisableTiming);
        cudaEventCreateWithFlags(&evB, cudaEventDisableTiming);
        cudaEventCreateWithFlags(&evC, cudaEventDisableTiming);
        cudaFuncSetAttribute(k_gemm1, cudaFuncAttributeMaxDynamicSharedMemorySize, GEMM_SMEM);
        cudaFuncSetAttribute(k_gemm2, cudaFuncAttributeMaxDynamicSharedMemorySize, GEMM_SMEM);
    }

    // ---- immediate fork ----
    cudaEventRecord(evRoot, 0);
    cudaStreamWaitEvent(sA, evRoot, 0);
    cudaStreamWaitEvent(sB, evRoot, 0);

    // Chain A: initA -> deg -> scans -> fill.   Chain B: initB -> cnt -> gemm1 -> bn1 -> gemm2.
    k_initA<<<(NUN + 255) / 256, 256, 0, sA>>>();                       // launch 0
    k_initB<<<(NPOOL + 255) / 256, 256, 0, sB>>>();                     // launch 1
    k_cnt<<<(NUN + 255) / 256, 256, 0, sB>>>(cluster);                  // launch 2
    k_gemm1<<<NB1, 256, GEMM_SMEM, sB>>>(x, W1, score, b1);             // launch 3 (ncu)
    k_deg<<<(NEDGE + 255) / 256, 256, 0, sA>>>(dstA);                   // launch 4
    k_scanA<<<NSCAN, SCAN_BLK, 0, sA>>>();                              // launch 5
    k_scanB<<<1, 32, 0, sA>>>();                                        // launch 6
    k_scanC<<<NSCAN, SCAN_BLK, 0, sA>>>();                              // launch 7
    k_fill<<<(NEDGE + 255) / 256, 256, 0, sA>>>(srcA, dstA, cluster);   // launch 8
    k_bn1<<<1, 1024, 0, sB>>>(g1, be1);                                 // launch 9
    k_gemm2<<<NB1, 256, GEMM_SMEM, sB>>>(Wg, score, b1);                // launch 10

    // Chain C: output tail passthrough
    if (extra > 0) {
        cudaStreamWaitEvent(sC, evRoot, 0);
        k_tail<<<(extra + 255) / 256, 256, 0, sC>>>(ei, batch, out, extra);
        cudaEventRecord(evC, sC);
    }

    // ---- join ----
    cudaEventRecord(evA, sA);
    cudaEventRecord(evB, sB);
    cudaStreamWaitEvent(0, evA, 0);
    cudaStreamWaitEvent(0, evB, 0);
    if (extra > 0) cudaStreamWaitEvent(0, evC, 0);

    // ---- serial epilogue on the captured stream ----
    k_gather<<<NUN / 16, 256>>>(cluster, bg);
    k_stats2<<<STATS_GRID, 256>>>();
    k_meanvar2<<<1, 64>>>(g2, be2);
    k_final<<<(NUN * 16 + 255) / 256, 256>>>(out);
}

// round 15
// speedup vs baseline: 1.0441x; 1.0441x over previous
#include <cuda_runtime.h>
#include <cuda_fp16.h>

#define NPOOL 100000
#define NUN   200000
#define NEDGE 1200000
#define CH    64
#define EPSV  1e-5f

#define SCAN_BLK   512
#define SCAN_ITEMS 8
#define SCAN_TILE  (SCAN_BLK * SCAN_ITEMS)                 // 4096
#define NSCAN      ((NUN + SCAN_TILE - 1) / SCAN_TILE)     // 49
#define GROWS      128                                     // gemm rows per block
#define NB1        ((NPOOL + GROWS - 1) / GROWS)           // 782 gemm blocks
#define GEMM_SMEM  ((4096 + GROWS * 68) * 4)               // 51200 bytes
#define STATS_GRID 296

// ---------------- scratch ----------------
__device__ __half2 g_Pp [NPOOL * 32];     // x @ W1 (fp16, 128B/row)
__device__ __half2 g_HWp[NPOOL * 32];     // relu(bn1(...)) @ Wg (fp16, 128B/row)
__device__ __half2 g_ACCh[NUN * 32];      // GCN result pre-BN2 (fp16, 128B/row)
__device__ int     g_indeg[NUN];
__device__ float   g_dis[NUN];
__device__ int     g_cnt[NPOOL];
__device__ int     g_off[NUN + 1];
__device__ int     g_cur[NUN];
__device__ int2    g_ent[NEDGE];          // {cluster[src], bits(dis[src])} by dst
__device__ int     g_bsum[NSCAN], g_bpre[NSCAN];
__device__ float   g_p1s[64 * NB1];       // BN1 per-block partials
__device__ float   g_p1q[64 * NB1];
__device__ double  g_s2[CH], g_q2[CH];
__device__ float   g_scale1[CH], g_shift1[CH], g_scale2[CH], g_shift2[CH];

// ---------------- init ----------------
__global__ void k_init() {
    int i = blockIdx.x * blockDim.x + threadIdx.x;
    if (i < NUN)   g_indeg[i] = 0;
    if (i < NPOOL) g_cnt[i] = 0;
    if (i < CH) { g_s2[i] = 0.0; g_q2[i] = 0.0; }
}

// ---------------- in-degree (dst) + cluster histogram ----------------
__global__ void k_deg_hist(const int* __restrict__ dst, const int* __restrict__ cluster) {
    int i = blockIdx.x * blockDim.x + threadIdx.x;
    if (i < NEDGE) atomicAdd(&g_indeg[dst[i]], 1);
    if (i < NUN)   atomicAdd(&g_cnt[cluster[i]], 1);
}

// ---------------- scan A: per-block sums of indeg; also compute dis ----------------
__global__ __launch_bounds__(SCAN_BLK) void k_scanA() {
    __shared__ int sh[SCAN_BLK];
    int t = threadIdx.x;
    int base = blockIdx.x * SCAN_TILE + t * SCAN_ITEMS;
    int s = 0;
#pragma unroll
    for (int i = 0; i < SCAN_ITEMS; i++) {
        int idx = base + i;
        if (idx < NUN) {
            int dg = g_indeg[idx];
            s += dg;
            g_dis[idx] = rsqrtf((float)dg + 1.0f);
        }
    }
    sh[t] = s;
    __syncthreads();
    for (int off = SCAN_BLK / 2; off > 0; off >>= 1) {
        if (t < off) sh[t] += sh[t + off];
        __syncthreads();
    }
    if (t == 0) g_bsum[blockIdx.x] = sh[0];
}

// ---------------- GEMM1: Pp(fp16) = x @ W1 ; fused BN1 partials ----------------
// 256 threads, 128 rows/block, dynamic smem, forced 4 blocks/SM.
__global__ __launch_bounds__(256, 4) void k_gemm1(const float* __restrict__ x,
                                                  const float* __restrict__ W,
                                                  const float* __restrict__ score,
                                                  const float* __restrict__ b1) {
    extern __shared__ float smem[];
    float* Ws = smem;              // 64*64
    float* Xs = smem + 4096;       // 128*68
    int t = threadIdx.x;
    for (int i = t; i < 1024; i += 256)
        ((float4*)Ws)[i] = ((const float4*)W)[i];
    int row0 = blockIdx.x * GROWS;
#pragma unroll
    for (int j = 0; j < 8; j++) {
        int i = t + j * 256;
        int r = i >> 4, c4 = i & 15;
        int row = row0 + r;
        float4 v = make_float4(0.f, 0.f, 0.f, 0.f);
        if (row < NPOOL) v = ((const float4*)(x + (size_t)row * CH))[c4];
        *((float4*)(Xs + r * 68 + c4 * 4)) = v;
    }
    __syncthreads();
    int cg = t & 7, rg = t >> 3;   // rg 0..31
    float acc[4][8];
#pragma unroll
    for (int r = 0; r < 4; r++)
#pragma unroll
        for (int c = 0; c < 8; c++) acc[r][c] = 0.f;
    for (int k = 0; k < 64; k++) {
        float4 w0 = *((float4*)(Ws + k * 64 + cg * 8));
        float4 w1 = *((float4*)(Ws + k * 64 + cg * 8 + 4));
#pragma unroll
        for (int r = 0; r < 4; r++) {
            float xv = Xs[(rg + 32 * r) * 68 + k];
            acc[r][0] = fmaf(xv, w0.x, acc[r][0]);
            acc[r][1] = fmaf(xv, w0.y, acc[r][1]);
            acc[r][2] = fmaf(xv, w0.z, acc[r][2]);
            acc[r][3] = fmaf(xv, w0.w, acc[r][3]);
            acc[r][4] = fmaf(xv, w1.x, acc[r][4]);
            acc[r][5] = fmaf(xv, w1.y, acc[r][5]);
            acc[r][6] = fmaf(xv, w1.z, acc[r][6]);
            acc[r][7] = fmaf(xv, w1.w, acc[r][7]);
        }
    }
#pragma unroll
    for (int r = 0; r < 4; r++) {
        int row = row0 + rg + 32 * r;
        if (row < NPOOL) {
            __half2 h0 = __floats2half2_rn(acc[r][0], acc[r][1]);
            __half2 h1 = __floats2half2_rn(acc[r][2], acc[r][3]);
            __half2 h2 = __floats2half2_rn(acc[r][4], acc[r][5]);
            __half2 h3 = __floats2half2_rn(acc[r][6], acc[r][7]);
            uint4 u;
            u.x = *reinterpret_cast<unsigned*>(&h0);
            u.y = *reinterpret_cast<unsigned*>(&h1);
            u.z = *reinterpret_cast<unsigned*>(&h2);
            u.w = *reinterpret_cast<unsigned*>(&h3);
            *((uint4*)(g_Pp + (size_t)row * 32 + cg * 4)) = u;
        }
    }
    // ---- fused BN1 partials (exact fp32 registers) ----
    float4 b1a = ((const float4*)b1)[cg * 2];
    float4 b1b = ((const float4*)b1)[cg * 2 + 1];
    float bcol[8] = {b1a.x, b1a.y, b1a.z, b1a.w, b1b.x, b1b.y, b1b.z, b1b.w};
    float s8[8], q8[8];
#pragma unroll
    for (int c = 0; c < 8; c++) { s8[c] = 0.f; q8[c] = 0.f; }
#pragma unroll
    for (int r = 0; r < 4; r++) {
        int row = row0 + rg + 32 * r;
        if (row < NPOOL) {
            float fw = (float)g_cnt[row];
            if (fw > 0.f) {
                float inv = 1.0f / score[row];
#pragma unroll
                for (int c = 0; c < 8; c++) {
                    float v = fmaf(acc[r][c], inv, bcol[c]);
                    s8[c] = fmaf(fw, v, s8[c]);
                    q8[c] = fmaf(fw * v, v, q8[c]);
                }
            }
        }
    }
    __syncthreads();                 // done reading Xs; reuse it
    float* Ss = Xs;                  // [32][64]
    float* Qs = Xs + 2048;           // [32][64]
#pragma unroll
    for (int c = 0; c < 8; c++) {
        Ss[rg * 64 + cg * 8 + c] = s8[c];
        Qs[rg * 64 + cg * 8 + c] = q8[c];
    }
    __syncthreads();
    if (t < 128) {
        int c = t & 63;
        const float* base = (t < 64) ? Ss : Qs;
        float s = 0.f;
#pragma unroll
        for (int i = 0; i < 32; i++) s += base[i * 64 + c];
        if (t < 64) g_p1s[c * NB1 + blockIdx.x] = s;
        else        g_p1q[c * NB1 + blockIdx.x] = s;
    }
}

// ---------------- BN1 reduce + finalize ----------------
__global__ __launch_bounds__(1024) void k_bn1(const float* __restrict__ g1,
                                              const float* __restrict__ be1) {
    int t = threadIdx.x;
    int wid = t >> 5, lane = t & 31;
#pragma unroll
    for (int ci = 0; ci < 2; ci++) {
        int c = wid * 2 + ci;
        double s = 0.0, q = 0.0;
        for (int i = lane; i < NB1; i += 32) {
            s += (double)g_p1s[c * NB1 + i];
            q += (double)g_p1q[c * NB1 + i];
        }
#pragma unroll
        for (int o = 16; o > 0; o >>= 1) {
            s += __shfl_down_sync(0xFFFFFFFFu, s, o);
            q += __shfl_down_sync(0xFFFFFFFFu, q, o);
        }
        if (lane == 0) {
            double invN = 1.0 / (double)NUN;
            float mu = (float)(s * invN);
            float var = (float)(q * invN) - mu * mu;
            if (var < 0.f) var = 0.f;
            float rs = rsqrtf(var + EPSV);
            float sc = g1[c] * rs;
            g_scale1[c] = sc;
            g_shift1[c] = be1[c] - mu * sc;
        }
    }
}

// ---------------- scan B ----------------
__global__ void k_scanB() {
    if (threadIdx.x == 0) {
        int run = 0;
        for (int b = 0; b < NSCAN; b++) { g_bpre[b] = run; run += g_bsum[b]; }
        g_off[NUN] = run;
    }
}

// ---------------- scan C ----------------
__global__ __launch_bounds__(SCAN_BLK) void k_scanC() {
    __shared__ int wsum[16];
    int t = threadIdx.x;
    int lane = t & 31, wid = t >> 5;
    int base = blockIdx.x * SCAN_TILE + t * SCAN_ITEMS;
    int v[SCAN_ITEMS];
    int s = 0;
#pragma unroll
    for (int i = 0; i < SCAN_ITEMS; i++) {
        int idx = base + i;
        v[i] = (idx < NUN) ? g_indeg[idx] : 0;
        s += v[i];
    }
    int incl = s;
#pragma unroll
    for (int off = 1; off < 32; off <<= 1) {
        int n = __shfl_up_sync(0xFFFFFFFFu, incl, off);
        if (lane >= off) incl += n;
    }
    if (lane == 31) wsum[wid] = incl;
    __syncthreads();
    if (wid == 0) {
        int x = (lane < 16) ? wsum[lane] : 0;
        int xi = x;
#pragma unroll
        for (int off = 1; off < 32; off <<= 1) {
            int n = __shfl_up_sync(0xFFFFFFFFu, xi, off);
            if (lane >= off) xi += n;
        }
        if (lane < 16) wsum[lane] = xi - x;
    }
    __syncthreads();
    int run = g_bpre[blockIdx.x] + wsum[wid] + (incl - s);
#pragma unroll
    for (int i = 0; i < SCAN_ITEMS; i++) {
        int idx = base + i;
        if (idx < NUN) { g_off[idx] = run; g_cur[idx] = run; run += v[i]; }
    }
}

// ---------------- fill ----------------
__global__ void k_fill(const int* __restrict__ src, const int* __restrict__ dst,
                       const int* __restrict__ cluster) {
    int e = blockIdx.x * blockDim.x + threadIdx.x;
    if (e < NEDGE) {
        int s = src[e], d = dst[e];
        int pos = atomicAdd(&g_cur[d], 1);
        g_ent[pos] = make_int2(cluster[s], __float_as_int(g_dis[s]));
    }
}

// ---------------- GEMM2: HWp(fp16) = relu(bn1(Pp/score + b1)) @ Wg ----------------
__global__ __launch_bounds__(256, 4) void k_gemm2(const float* __restrict__ Wg,
                                                  const float* __restrict__ score,
                                                  const float* __restrict__ b1) {
    extern __shared__ float smem[];
    float* Ws = smem;
    float* Xs = smem + 4096;
    int t = threadIdx.x;
    for (int i = t; i < 1024; i += 256)
        ((float4*)Ws)[i] = ((const float4*)Wg)[i];
    int row0 = blockIdx.x * GROWS;
#pragma unroll
    for (int j = 0; j < 8; j++) {
        int i = t + j * 256;
        int r = i >> 4, c4 = i & 15;
        int row = row0 + r;
        float4 v = make_float4(0.f, 0.f, 0.f, 0.f);
        if (row < NPOOL) {
            float inv = 1.0f / score[row];
            uint2 u = *((const uint2*)(g_Pp + (size_t)row * 32 + c4 * 2));
            float2 pa = __half22float2(*reinterpret_cast<__half2*>(&u.x));
            float2 pb = __half22float2(*reinterpret_cast<__half2*>(&u.y));
            float4 a   = ((const float4*)g_scale1)[c4];
            float4 sh  = ((const float4*)g_shift1)[c4];
            float4 b1v = ((const float4*)b1)[c4];
            v.x = fmaxf(fmaf(pa.x * inv, a.x, fmaf(b1v.x, a.x, sh.x)), 0.f);
            v.y = fmaxf(fmaf(pa.y * inv, a.y, fmaf(b1v.y, a.y, sh.y)), 0.f);
            v.z = fmaxf(fmaf(pb.x * inv, a.z, fmaf(b1v.z, a.z, sh.z)), 0.f);
            v.w = fmaxf(fmaf(pb.y * inv, a.w, fmaf(b1v.w, a.w, sh.w)), 0.f);
        }
        *((float4*)(Xs + r * 68 + c4 * 4)) = v;
    }
    __syncthreads();
    int cg = t & 7, rg = t >> 3;
    float acc[4][8];
#pragma unroll
    for (int r = 0; r < 4; r++)
#pragma unroll
        for (int c = 0; c < 8; c++) acc[r][c] = 0.f;
    for (int k = 0; k < 64; k++) {
        float4 w0 = *((float4*)(Ws + k * 64 + cg * 8));
        float4 w1 = *((float4*)(Ws + k * 64 + cg * 8 + 4));
#pragma unroll
        for (int r = 0; r < 4; r++) {
            float xv = Xs[(rg + 32 * r) * 68 + k];
            acc[r][0] = fmaf(xv, w0.x, acc[r][0]);
            acc[r][1] = fmaf(xv, w0.y, acc[r][1]);
            acc[r][2] = fmaf(xv, w0.z, acc[r][2]);
            acc[r][3] = fmaf(xv, w0.w, acc[r][3]);
            acc[r][4] = fmaf(xv, w1.x, acc[r][4]);
            acc[r][5] = fmaf(xv, w1.y, acc[r][5]);
            acc[r][6] = fmaf(xv, w1.z, acc[r][6]);
            acc[r][7] = fmaf(xv, w1.w, acc[r][7]);
        }
    }
#pragma unroll
    for (int r = 0; r < 4; r++) {
        int row = row0 + rg + 32 * r;
        if (row < NPOOL) {
            __half2 h0 = __floats2half2_rn(acc[r][0], acc[r][1]);
            __half2 h1 = __floats2half2_rn(acc[r][2], acc[r][3]);
            __half2 h2 = __floats2half2_rn(acc[r][4], acc[r][5]);
            __half2 h3 = __floats2half2_rn(acc[r][6], acc[r][7]);
            uint4 u;
            u.x = *reinterpret_cast<unsigned*>(&h0);
            u.y = *reinterpret_cast<unsigned*>(&h1);
            u.z = *reinterpret_cast<unsigned*>(&h2);
            u.w = *reinterpret_cast<unsigned*>(&h3);
            *((uint4*)(g_HWp + (size_t)row * 32 + cg * 4)) = u;
        }
    }
}

// ---------------- gather: ACCh(fp16) = bg + HWp[cluster[d]]*dis^2 + in-edge sum ----------------
__global__ __launch_bounds__(256) void k_gather(const int* __restrict__ cluster,
                                                const float* __restrict__ bg) {
    int t = threadIdx.x;
    int rowIdx = t >> 4;
    int q = t & 15;
    int d = blockIdx.x * 16 + rowIdx;            // NUN % 16 == 0
    int   c0 = cluster[d];
    float dd = g_dis[d];
    float d2 = dd * dd;
    float4 a0 = ((const float4*)bg)[q];
    float4 a1 = make_float4(0.f, 0.f, 0.f, 0.f);
    float4 a2 = make_float4(0.f, 0.f, 0.f, 0.f);
    float4 a3 = make_float4(0.f, 0.f, 0.f, 0.f);
    {
        uint2 u = *((const uint2*)(g_HWp + (size_t)c0 * 32) + q);
        float2 fa = __half22float2(*reinterpret_cast<__half2*>(&u.x));
        float2 fb = __half22float2(*reinterpret_cast<__half2*>(&u.y));
        a0.x = fmaf(fa.x, d2, a0.x);
        a0.y = fmaf(fa.y, d2, a0.y);
        a0.z = fmaf(fb.x, d2, a0.z);
        a0.w = fmaf(fb.y, d2, a0.w);
    }
    int beg = g_off[d], end = g_off[d + 1];
    int j = beg;
    for (; j + 4 <= end; j += 4) {
        int2 e0 = g_ent[j];
        int2 e1 = g_ent[j + 1];
        int2 e2 = g_ent[j + 2];
        int2 e3 = g_ent[j + 3];
        float k0 = __int_as_float(e0.y) * dd;
        float k1 = __int_as_float(e1.y) * dd;
        float k2 = __int_as_float(e2.y) * dd;
        float k3 = __int_as_float(e3.y) * dd;
        uint2 u0 = *((const uint2*)(g_HWp + (size_t)e0.x * 32) + q);
        uint2 u1 = *((const uint2*)(g_HWp + (size_t)e1.x * 32) + q);
        uint2 u2 = *((const uint2*)(g_HWp + (size_t)e2.x * 32) + q);
        uint2 u3 = *((const uint2*)(g_HWp + (size_t)e3.x * 32) + q);
        float2 fa0 = __half22float2(*reinterpret_cast<__half2*>(&u0.x));
        float2 fb0 = __half22float2(*reinterpret_cast<__half2*>(&u0.y));
        float2 fa1 = __half22float2(*reinterpret_cast<__half2*>(&u1.x));
        float2 fb1 = __half22float2(*reinterpret_cast<__half2*>(&u1.y));
        float2 fa2 = __half22float2(*reinterpret_cast<__half2*>(&u2.x));
        float2 fb2 = __half22float2(*reinterpret_cast<__half2*>(&u2.y));
        float2 fa3 = __half22float2(*reinterpret_cast<__half2*>(&u3.x));
        float2 fb3 = __half22float2(*reinterpret_cast<__half2*>(&u3.y));
        a0.x = fmaf(fa0.x, k0, a0.x); a0.y = fmaf(fa0.y, k0, a0.y);
        a0.z = fmaf(fb0.x, k0, a0.z); a0.w = fmaf(fb0.y, k0, a0.w);
        a1.x = fmaf(fa1.x, k1, a1.x); a1.y = fmaf(fa1.y, k1, a1.y);
        a1.z = fmaf(fb1.x, k1, a1.z); a1.w = fmaf(fb1.y, k1, a1.w);
        a2.x = fmaf(fa2.x, k2, a2.x); a2.y = fmaf(fa2.y, k2, a2.y);
        a2.z = fmaf(fb2.x, k2, a2.z); a2.w = fmaf(fb2.y, k2, a2.w);
        a3.x = fmaf(fa3.x, k3, a3.x); a3.y = fmaf(fa3.y, k3, a3.y);
        a3.z = fmaf(fb3.x, k3, a3.z); a3.w = fmaf(fb3.y, k3, a3.w);
    }
    for (; j < end; j++) {
        int2 e0 = g_ent[j];
        float k0 = __int_as_float(e0.y) * dd;
        uint2 u0 = *((const uint2*)(g_HWp + (size_t)e0.x * 32) + q);
        float2 fa0 = __half22float2(*reinterpret_cast<__half2*>(&u0.x));
        float2 fb0 = __half22float2(*reinterpret_cast<__half2*>(&u0.y));
        a0.x = fmaf(fa0.x, k0, a0.x); a0.y = fmaf(fa0.y, k0, a0.y);
        a0.z = fmaf(fb0.x, k0, a0.z); a0.w = fmaf(fb0.y, k0, a0.w);
    }
    __half2 h0 = __floats2half2_rn((a0.x + a1.x) + (a2.x + a3.x),
                                   (a0.y + a1.y) + (a2.y + a3.y));
    __half2 h1 = __floats2half2_rn((a0.z + a1.z) + (a2.z + a3.z),
                                   (a0.w + a1.w) + (a2.w + a3.w));
    uint2 u;
    u.x = *reinterpret_cast<unsigned*>(&h0);
    u.y = *reinterpret_cast<unsigned*>(&h1);
    *((uint2*)(g_ACCh + (size_t)d * 32 + q * 2)) = u;
}

// ---------------- BN2 stats over fp16 ACC ----------------
__global__ __launch_bounds__(256) void k_stats2() {
    int t = threadIdx.x;
    float4 s4 = make_float4(0.f, 0.f, 0.f, 0.f);
    float4 q4 = make_float4(0.f, 0.f, 0.f, 0.f);
    const int total = NUN * 16;                 // uint2 units (4 cols each)
    int stride = gridDim.x * blockDim.x;
#pragma unroll 4
    for (int i = blockIdx.x * blockDim.x + t; i < total; i += stride) {
        uint2 u = ((const uint2*)g_ACCh)[i];
        float2 a = __half22float2(*reinterpret_cast<__half2*>(&u.x));
        float2 b = __half22float2(*reinterpret_cast<__half2*>(&u.y));
        s4.x += a.x; q4.x = fmaf(a.x, a.x, q4.x);
        s4.y += a.y; q4.y = fmaf(a.y, a.y, q4.y);
        s4.z += b.x; q4.z = fmaf(b.x, b.x, q4.z);
        s4.w += b.y; q4.w = fmaf(b.y, b.y, q4.w);
    }
    s4.x += __shfl_xor_sync(0xFFFFFFFFu, s4.x, 16);
    s4.y += __shfl_xor_sync(0xFFFFFFFFu, s4.y, 16);
    s4.z += __shfl_xor_sync(0xFFFFFFFFu, s4.z, 16);
    s4.w += __shfl_xor_sync(0xFFFFFFFFu, s4.w, 16);
    q4.x += __shfl_xor_sync(0xFFFFFFFFu, q4.x, 16);
    q4.y += __shfl_xor_sync(0xFFFFFFFFu, q4.y, 16);
    q4.z += __shfl_xor_sync(0xFFFFFFFFu, q4.z, 16);
    q4.w += __shfl_xor_sync(0xFFFFFFFFu, q4.w, 16);
    __shared__ float shs[8][64], shq[8][64];
    int wid = t >> 5, lane = t & 31;
    if (lane < 16) {
        shs[wid][lane * 4 + 0] = s4.x;
        shs[wid][lane * 4 + 1] = s4.y;
        shs[wid][lane * 4 + 2] = s4.z;
        shs[wid][lane * 4 + 3] = s4.w;
        shq[wid][lane * 4 + 0] = q4.x;
        shq[wid][lane * 4 + 1] = q4.y;
        shq[wid][lane * 4 + 2] = q4.z;
        shq[wid][lane * 4 + 3] = q4.w;
    }
    __syncthreads();
    if (t < 64) {
        float s = 0.f, qq = 0.f;
#pragma unroll
        for (int w = 0; w < 8; w++) { s += shs[w][t]; qq += shq[w][t]; }
        atomicAdd(&g_s2[t], (double)s);
        atomicAdd(&g_q2[t], (double)qq);
    }
}

// ---------------- finalize BN2 params ----------------
__global__ void k_meanvar2(const float* __restrict__ g, const float* __restrict__ b) {
    int t = threadIdx.x;
    if (t < CH) {
        double s = g_s2[t];
        double q = g_q2[t];
        double invN = 1.0 / (double)NUN;
        float mu = (float)(s * invN);
        float var = (float)(q * invN) - mu * mu;
        if (var < 0.f) var = 0.f;
        float rs = rsqrtf(var + EPSV);
        float sc = g[t] * rs;
        g_scale2[t] = sc;
        g_shift2[t] = b[t] - mu * sc;
    }
}

// ---------------- final: out = relu(bn2(ACCh)) ----------------
__global__ void k_final(float* __restrict__ out) {
    int i4 = blockIdx.x * blockDim.x + threadIdx.x;
    if (i4 < NUN * 16) {
        int c4 = i4 & 15;
        uint2 u = ((const uint2*)g_ACCh)[i4];
        float2 a = __half22float2(*reinterpret_cast<__half2*>(&u.x));
        float2 b = __half22float2(*reinterpret_cast<__half2*>(&u.y));
        float4 sc = ((const float4*)g_scale2)[c4];
        float4 sh = ((const float4*)g_shift2)[c4];
        float4 o;
        o.x = fmaxf(fmaf(a.x, sc.x, sh.x), 0.f);
        o.y = fmaxf(fmaf(a.y, sc.y, sh.y), 0.f);
        o.z = fmaxf(fmaf(b.x, sc.z, sh.z), 0.f);
        o.w = fmaxf(fmaf(b.y, sc.w, sh.w), 0.f);
        ((float4*)out)[i4] = o;
    }
}

// ---------------- optional tail ----------------
__global__ void k_tail(const int* __restrict__ ei, const int* __restrict__ batch,
                       float* __restrict__ out, int extra) {
    int i = blockIdx.x * blockDim.x + threadIdx.x;
    if (i < extra) {
        float v;
        if (i < 2 * NEDGE) v = (float)ei[i];
        else {
            int j = i - 2 * NEDGE;
            v = (j < NUN) ? (float)batch[j] : 0.f;
        }
        out[NUN * CH + i] = v;
    }
}

// ---------------- launch (round-11 topology + faster GEMM tiles) ----------------
extern "C" void kernel_launch(void* const* d_in, const int* in_sizes, int n_in,
                              void* d_out, int out_size) {
    const float* x       = (const float*)d_in[0];
    const int*   ei      = (const int*)  d_in[1];
    const int*   batch   = (const int*)  d_in[2];
    const int*   cluster = (const int*)  d_in[3];
    const float* score   = (const float*)d_in[4];
    const float* W1      = (const float*)d_in[5];
    const float* b1      = (const float*)d_in[6];
    const float* g1      = (const float*)d_in[7];
    const float* be1     = (const float*)d_in[8];
    const float* Wg      = (const float*)d_in[9];
    const float* bg      = (const float*)d_in[10];
    const float* g2      = (const float*)d_in[11];
    const float* be2     = (const float*)d_in[12];
    const int* srcA = ei;
    const int* dstA = ei + NEDGE;
    float* out = (float*)d_out;
    int extra = out_size - NUN * CH;

    static cudaStream_t sA = 0, sB = 0, sC = 0;
    static cudaEvent_t evRoot = 0, evA = 0, evB = 0, evC = 0;
    if (!sA) {
        cudaStreamCreateWithFlags(&sA, cudaStreamNonBlocking);
        cudaStreamCreateWithFlags(&sB, cudaStreamNonBlocking);
        cudaStreamCreateWithFlags(&sC, cudaStreamNonBlocking);
        cudaEventCreateWithFlags(&evRoot, cudaEventDisableTiming);
        cudaEventCreateWithFlags(&evA, cudaEventDisableTiming);
        cudaEventCreateWithFlags(&evB, cudaEventDisableTiming);
        cudaEventCreateWithFlags(&evC, cudaEventDisableTiming);
        cudaFuncSetAttribute(k_gemm1, cudaFuncAttributeMaxDynamicSharedMemorySize, GEMM_SMEM);
        cudaFuncSetAttribute(k_gemm2, cudaFuncAttributeMaxDynamicSharedMemorySize, GEMM_SMEM);
    }

    // ---- serial prologue on the captured stream (round-11 proven) ----
    k_init<<<(NUN + 255) / 256, 256>>>();                              // launch 0
    k_deg_hist<<<(NEDGE + 255) / 256, 256>>>(dstA, cluster);           // launch 1

    // ---- fork ----
    cudaEventRecord(evRoot, 0);
    cudaStreamWaitEvent(sA, evRoot, 0);
    cudaStreamWaitEvent(sB, evRoot, 0);

    // Chain A (scan + fill) on sA; Chain B (GEMMs) on sB.
    k_scanA<<<NSCAN, SCAN_BLK, 0, sA>>>();                             // launch 2
    k_gemm1<<<NB1, 256, GEMM_SMEM, sB>>>(x, W1, score, b1);            // launch 3 (ncu)
    k_scanB<<<1, 32, 0, sA>>>();                                       // launch 4
    k_scanC<<<NSCAN, SCAN_BLK, 0, sA>>>();                             // launch 5
    k_fill<<<(NEDGE + 255) / 256, 256, 0, sA>>>(srcA, dstA, cluster);  // launch 6
    k_bn1<<<1, 1024, 0, sB>>>(g1, be1);                                // launch 7
    k_gemm2<<<NB1, 256, GEMM_SMEM, sB>>>(Wg, score, b1);               // launch 8

    // Chain C: output tail passthrough
    if (extra > 0) {
        cudaStreamWaitEvent(sC, evRoot, 0);
        k_tail<<<(extra + 255) / 256, 256, 0, sC>>>(ei, batch, out, extra);
        cudaEventRecord(evC, sC);
    }

    // ---- join ----
    cudaEventRecord(evA, sA);
    cudaEventRecord(evB, sB);
    cudaStreamWaitEvent(0, evA, 0);
    cudaStreamWaitEvent(0, evB, 0);
    if (extra > 0) cudaStreamWaitEvent(0, evC, 0);

    // ---- serial epilogue on the captured stream ----
    k_gather<<<NUN / 16, 256>>>(cluster, bg);
    k_stats2<<<STATS_GRID, 256>>>();
    k_meanvar2<<<1, 64>>>(g2, be2);
    k_final<<<(NUN * 16 + 255) / 256, 256>>>(out);
}

// round 17
// speedup vs baseline: 1.0805x; 1.0349x over previous
#include <cuda_runtime.h>
#include <cuda_fp16.h>

#define NPOOL 100000
#define NUN   200000
#define NEDGE 1200000
#define CH    64
#define EPSV  1e-5f

#define SCAN_BLK   512
#define SCAN_ITEMS 8
#define SCAN_TILE  (SCAN_BLK * SCAN_ITEMS)                 // 4096
#define NSCAN      ((NUN + SCAN_TILE - 1) / SCAN_TILE)     // 49
#define GROWS      128                                     // gemm rows per block
#define NB1        ((NPOOL + GROWS - 1) / GROWS)           // 782 gemm blocks
#define GEMM_SMEM  ((4096 + GROWS * 68) * 4)               // 51200 bytes
#define STATS_GRID 296

// ---------------- scratch ----------------
__device__ __half2 g_Pp [NPOOL * 32];     // x @ W1 (fp16, 128B/row)
__device__ __half2 g_HWp[NPOOL * 32];     // relu(bn1(...)) @ Wg (fp16, 128B/row)
__device__ __half2 g_ACCh[NUN * 32];      // GCN result pre-BN2 (fp16, 128B/row)
__device__ int     g_indeg[NUN];
__device__ float   g_dis[NUN];
__device__ int     g_cnt[NPOOL];
__device__ int     g_off[NUN + 1];
__device__ int     g_cur[NUN];
__device__ int2    g_ent[NEDGE];          // {cluster[src], bits(dis[src])} by dst
__device__ int     g_bsum[NSCAN], g_bpre[NSCAN];
__device__ float   g_p1s[64 * NB1];       // BN1 per-block partials
__device__ float   g_p1q[64 * NB1];
__device__ double  g_s2[CH], g_q2[CH];
__device__ float   g_scale1[CH], g_shift1[CH], g_scale2[CH], g_shift2[CH];

// ---------------- init ----------------
__global__ void k_init() {
    int i = blockIdx.x * blockDim.x + threadIdx.x;
    if (i < NUN)   g_indeg[i] = 0;
    if (i < NPOOL) g_cnt[i] = 0;
    if (i < CH) { g_s2[i] = 0.0; g_q2[i] = 0.0; }
}

// ---------------- in-degree (dst) + cluster histogram ----------------
__global__ void k_deg_hist(const int* __restrict__ dst, const int* __restrict__ cluster) {
    int i = blockIdx.x * blockDim.x + threadIdx.x;
    if (i < NEDGE) atomicAdd(&g_indeg[dst[i]], 1);
    if (i < NUN)   atomicAdd(&g_cnt[cluster[i]], 1);
}

// ---------------- scan A: per-block sums of indeg; also compute dis ----------------
__global__ __launch_bounds__(SCAN_BLK) void k_scanA() {
    __shared__ int sh[SCAN_BLK];
    int t = threadIdx.x;
    int base = blockIdx.x * SCAN_TILE + t * SCAN_ITEMS;
    int s = 0;
#pragma unroll
    for (int i = 0; i < SCAN_ITEMS; i++) {
        int idx = base + i;
        if (idx < NUN) {
            int dg = g_indeg[idx];
            s += dg;
            g_dis[idx] = rsqrtf((float)dg + 1.0f);
        }
    }
    sh[t] = s;
    __syncthreads();
    for (int off = SCAN_BLK / 2; off > 0; off >>= 1) {
        if (t < off) sh[t] += sh[t + off];
        __syncthreads();
    }
    if (t == 0) g_bsum[blockIdx.x] = sh[0];
}

// ---------------- GEMM1: Pp(fp16) = x @ W1 ; fused BN1 partials ----------------
__global__ __launch_bounds__(256, 4) void k_gemm1(const float* __restrict__ x,
                                                  const float* __restrict__ W,
                                                  const float* __restrict__ score,
                                                  const float* __restrict__ b1) {
    extern __shared__ float smem[];
    float* Ws = smem;              // 64*64
    float* Xs = smem + 4096;       // 128*68
    int t = threadIdx.x;
    for (int i = t; i < 1024; i += 256)
        ((float4*)Ws)[i] = ((const float4*)W)[i];
    int row0 = blockIdx.x * GROWS;
#pragma unroll
    for (int j = 0; j < 8; j++) {
        int i = t + j * 256;
        int r = i >> 4, c4 = i & 15;
        int row = row0 + r;
        float4 v = make_float4(0.f, 0.f, 0.f, 0.f);
        if (row < NPOOL) v = ((const float4*)(x + (size_t)row * CH))[c4];
        *((float4*)(Xs + r * 68 + c4 * 4)) = v;
    }
    __syncthreads();
    int cg = t & 7, rg = t >> 3;   // rg 0..31
    float acc[4][8];
#pragma unroll
    for (int r = 0; r < 4; r++)
#pragma unroll
        for (int c = 0; c < 8; c++) acc[r][c] = 0.f;
    for (int k = 0; k < 64; k++) {
        float4 w0 = *((float4*)(Ws + k * 64 + cg * 8));
        float4 w1 = *((float4*)(Ws + k * 64 + cg * 8 + 4));
#pragma unroll
        for (int r = 0; r < 4; r++) {
            float xv = Xs[(rg + 32 * r) * 68 + k];
            acc[r][0] = fmaf(xv, w0.x, acc[r][0]);
            acc[r][1] = fmaf(xv, w0.y, acc[r][1]);
            acc[r][2] = fmaf(xv, w0.z, acc[r][2]);
            acc[r][3] = fmaf(xv, w0.w, acc[r][3]);
            acc[r][4] = fmaf(xv, w1.x, acc[r][4]);
            acc[r][5] = fmaf(xv, w1.y, acc[r][5]);
            acc[r][6] = fmaf(xv, w1.z, acc[r][6]);
            acc[r][7] = fmaf(xv, w1.w, acc[r][7]);
        }
    }
#pragma unroll
    for (int r = 0; r < 4; r++) {
        int row = row0 + rg + 32 * r;
        if (row < NPOOL) {
            __half2 h0 = __floats2half2_rn(acc[r][0], acc[r][1]);
            __half2 h1 = __floats2half2_rn(acc[r][2], acc[r][3]);
            __half2 h2 = __floats2half2_rn(acc[r][4], acc[r][5]);
            __half2 h3 = __floats2half2_rn(acc[r][6], acc[r][7]);
            uint4 u;
            u.x = *reinterpret_cast<unsigned*>(&h0);
            u.y = *reinterpret_cast<unsigned*>(&h1);
            u.z = *reinterpret_cast<unsigned*>(&h2);
            u.w = *reinterpret_cast<unsigned*>(&h3);
            *((uint4*)(g_Pp + (size_t)row * 32 + cg * 4)) = u;
        }
    }
    // ---- fused BN1 partials (exact fp32 registers) ----
    float4 b1a = ((const float4*)b1)[cg * 2];
    float4 b1b = ((const float4*)b1)[cg * 2 + 1];
    float bcol[8] = {b1a.x, b1a.y, b1a.z, b1a.w, b1b.x, b1b.y, b1b.z, b1b.w};
    float s8[8], q8[8];
#pragma unroll
    for (int c = 0; c < 8; c++) { s8[c] = 0.f; q8[c] = 0.f; }
#pragma unroll
    for (int r = 0; r < 4; r++) {
        int row = row0 + rg + 32 * r;
        if (row < NPOOL) {
            float fw = (float)g_cnt[row];
            if (fw > 0.f) {
                float inv = 1.0f / score[row];
#pragma unroll
                for (int c = 0; c < 8; c++) {
                    float v = fmaf(acc[r][c], inv, bcol[c]);
                    s8[c] = fmaf(fw, v, s8[c]);
                    q8[c] = fmaf(fw * v, v, q8[c]);
                }
            }
        }
    }
    __syncthreads();                 // done reading Xs; reuse it
    float* Ss = Xs;                  // [32][64]
    float* Qs = Xs + 2048;           // [32][64]
#pragma unroll
    for (int c = 0; c < 8; c++) {
        Ss[rg * 64 + cg * 8 + c] = s8[c];
        Qs[rg * 64 + cg * 8 + c] = q8[c];
    }
    __syncthreads();
    if (t < 128) {
        int c = t & 63;
        const float* base = (t < 64) ? Ss : Qs;
        float s = 0.f;
#pragma unroll
        for (int i = 0; i < 32; i++) s += base[i * 64 + c];
        if (t < 64) g_p1s[c * NB1 + blockIdx.x] = s;
        else        g_p1q[c * NB1 + blockIdx.x] = s;
    }
}

// ---------------- BN1 reduce + finalize ----------------
__global__ __launch_bounds__(1024) void k_bn1(const float* __restrict__ g1,
                                              const float* __restrict__ be1) {
    int t = threadIdx.x;
    int wid = t >> 5, lane = t & 31;
#pragma unroll
    for (int ci = 0; ci < 2; ci++) {
        int c = wid * 2 + ci;
        double s = 0.0, q = 0.0;
        for (int i = lane; i < NB1; i += 32) {
            s += (double)g_p1s[c * NB1 + i];
            q += (double)g_p1q[c * NB1 + i];
        }
#pragma unroll
        for (int o = 16; o > 0; o >>= 1) {
            s += __shfl_down_sync(0xFFFFFFFFu, s, o);
            q += __shfl_down_sync(0xFFFFFFFFu, q, o);
        }
        if (lane == 0) {
            double invN = 1.0 / (double)NUN;
            float mu = (float)(s * invN);
            float var = (float)(q * invN) - mu * mu;
            if (var < 0.f) var = 0.f;
            float rs = rsqrtf(var + EPSV);
            float sc = g1[c] * rs;
            g_scale1[c] = sc;
            g_shift1[c] = be1[c] - mu * sc;
        }
    }
}

// ---------------- scan B ----------------
__global__ void k_scanB() {
    if (threadIdx.x == 0) {
        int run = 0;
        for (int b = 0; b < NSCAN; b++) { g_bpre[b] = run; run += g_bsum[b]; }
        g_off[NUN] = run;
    }
}

// ---------------- scan C ----------------
__global__ __launch_bounds__(SCAN_BLK) void k_scanC() {
    __shared__ int wsum[16];
    int t = threadIdx.x;
    int lane = t & 31, wid = t >> 5;
    int base = blockIdx.x * SCAN_TILE + t * SCAN_ITEMS;
    int v[SCAN_ITEMS];
    int s = 0;
#pragma unroll
    for (int i = 0; i < SCAN_ITEMS; i++) {
        int idx = base + i;
        v[i] = (idx < NUN) ? g_indeg[idx] : 0;
        s += v[i];
    }
    int incl = s;
#pragma unroll
    for (int off = 1; off < 32; off <<= 1) {
        int n = __shfl_up_sync(0xFFFFFFFFu, incl, off);
        if (lane >= off) incl += n;
    }
    if (lane == 31) wsum[wid] = incl;
    __syncthreads();
    if (wid == 0) {
        int x = (lane < 16) ? wsum[lane] : 0;
        int xi = x;
#pragma unroll
        for (int off = 1; off < 32; off <<= 1) {
            int n = __shfl_up_sync(0xFFFFFFFFu, xi, off);
            if (lane >= off) xi += n;
        }
        if (lane < 16) wsum[lane] = xi - x;
    }
    __syncthreads();
    int run = g_bpre[blockIdx.x] + wsum[wid] + (incl - s);
#pragma unroll
    for (int i = 0; i < SCAN_ITEMS; i++) {
        int idx = base + i;
        if (idx < NUN) { g_off[idx] = run; g_cur[idx] = run; run += v[i]; }
    }
}

// ---------------- fill ----------------
__global__ void k_fill(const int* __restrict__ src, const int* __restrict__ dst,
                       const int* __restrict__ cluster) {
    int e = blockIdx.x * blockDim.x + threadIdx.x;
    if (e < NEDGE) {
        int s = src[e], d = dst[e];
        int pos = atomicAdd(&g_cur[d], 1);
        g_ent[pos] = make_int2(cluster[s], __float_as_int(g_dis[s]));
    }
}

// ---------------- GEMM2: HWp(fp16) = relu(bn1(Pp/score + b1)) @ Wg ----------------
__global__ __launch_bounds__(256, 4) void k_gemm2(const float* __restrict__ Wg,
                                                  const float* __restrict__ score,
                                                  const float* __restrict__ b1) {
    extern __shared__ float smem[];
    float* Ws = smem;
    float* Xs = smem + 4096;
    int t = threadIdx.x;
    for (int i = t; i < 1024; i += 256)
        ((float4*)Ws)[i] = ((const float4*)Wg)[i];
    int row0 = blockIdx.x * GROWS;
#pragma unroll
    for (int j = 0; j < 8; j++) {
        int i = t + j * 256;
        int r = i >> 4, c4 = i & 15;
        int row = row0 + r;
        float4 v = make_float4(0.f, 0.f, 0.f, 0.f);
        if (row < NPOOL) {
            float inv = 1.0f / score[row];
            uint2 u = *((const uint2*)(g_Pp + (size_t)row * 32 + c4 * 2));
            float2 pa = __half22float2(*reinterpret_cast<__half2*>(&u.x));
            float2 pb = __half22float2(*reinterpret_cast<__half2*>(&u.y));
            float4 a   = ((const float4*)g_scale1)[c4];
            float4 sh  = ((const float4*)g_shift1)[c4];
            float4 b1v = ((const float4*)b1)[c4];
            v.x = fmaxf(fmaf(pa.x * inv, a.x, fmaf(b1v.x, a.x, sh.x)), 0.f);
            v.y = fmaxf(fmaf(pa.y * inv, a.y, fmaf(b1v.y, a.y, sh.y)), 0.f);
            v.z = fmaxf(fmaf(pb.x * inv, a.z, fmaf(b1v.z, a.z, sh.z)), 0.f);
            v.w = fmaxf(fmaf(pb.y * inv, a.w, fmaf(b1v.w, a.w, sh.w)), 0.f);
        }
        *((float4*)(Xs + r * 68 + c4 * 4)) = v;
    }
    __syncthreads();
    int cg = t & 7, rg = t >> 3;
    float acc[4][8];
#pragma unroll
    for (int r = 0; r < 4; r++)
#pragma unroll
        for (int c = 0; c < 8; c++) acc[r][c] = 0.f;
    for (int k = 0; k < 64; k++) {
        float4 w0 = *((float4*)(Ws + k * 64 + cg * 8));
        float4 w1 = *((float4*)(Ws + k * 64 + cg * 8 + 4));
#pragma unroll
        for (int r = 0; r < 4; r++) {
            float xv = Xs[(rg + 32 * r) * 68 + k];
            acc[r][0] = fmaf(xv, w0.x, acc[r][0]);
            acc[r][1] = fmaf(xv, w0.y, acc[r][1]);
            acc[r][2] = fmaf(xv, w0.z, acc[r][2]);
            acc[r][3] = fmaf(xv, w0.w, acc[r][3]);
            acc[r][4] = fmaf(xv, w1.x, acc[r][4]);
            acc[r][5] = fmaf(xv, w1.y, acc[r][5]);
            acc[r][6] = fmaf(xv, w1.z, acc[r][6]);
            acc[r][7] = fmaf(xv, w1.w, acc[r][7]);
        }
    }
#pragma unroll
    for (int r = 0; r < 4; r++) {
        int row = row0 + rg + 32 * r;
        if (row < NPOOL) {
            __half2 h0 = __floats2half2_rn(acc[r][0], acc[r][1]);
            __half2 h1 = __floats2half2_rn(acc[r][2], acc[r][3]);
            __half2 h2 = __floats2half2_rn(acc[r][4], acc[r][5]);
            __half2 h3 = __floats2half2_rn(acc[r][6], acc[r][7]);
            uint4 u;
            u.x = *reinterpret_cast<unsigned*>(&h0);
            u.y = *reinterpret_cast<unsigned*>(&h1);
            u.z = *reinterpret_cast<unsigned*>(&h2);
            u.w = *reinterpret_cast<unsigned*>(&h3);
            *((uint4*)(g_HWp + (size_t)row * 32 + cg * 4)) = u;
        }
    }
}

// ---------------- gather: 8 threads/row, uint4 loads (higher MLP) ----------------
__global__ __launch_bounds__(256) void k_gather(const int* __restrict__ cluster,
                                                const float* __restrict__ bg) {
    int t = threadIdx.x;
    int rowIdx = t >> 3;                          // 0..31
    int q = t & 7;                                // uint4 index within 128B row
    int d = blockIdx.x * 32 + rowIdx;             // NUN % 32 == 0
    int   c0 = cluster[d];
    float dd = g_dis[d];
    float d2 = dd * dd;
    float4 a0 = ((const float4*)bg)[q * 2];
    float4 b0 = ((const float4*)bg)[q * 2 + 1];
    float4 a1 = make_float4(0.f, 0.f, 0.f, 0.f), b1r = a1;
    float4 a2 = a1, b2 = a1, a3 = a1, b3 = a1;
    {
        uint4 u = *((const uint4*)(g_HWp + (size_t)c0 * 32) + q);
        float2 f0 = __half22float2(*reinterpret_cast<__half2*>(&u.x));
        float2 f1 = __half22float2(*reinterpret_cast<__half2*>(&u.y));
        float2 f2 = __half22float2(*reinterpret_cast<__half2*>(&u.z));
        float2 f3 = __half22float2(*reinterpret_cast<__half2*>(&u.w));
        a0.x = fmaf(f0.x, d2, a0.x); a0.y = fmaf(f0.y, d2, a0.y);
        a0.z = fmaf(f1.x, d2, a0.z); a0.w = fmaf(f1.y, d2, a0.w);
        b0.x = fmaf(f2.x, d2, b0.x); b0.y = fmaf(f2.y, d2, b0.y);
        b0.z = fmaf(f3.x, d2, b0.z); b0.w = fmaf(f3.y, d2, b0.w);
    }
    int beg = g_off[d], end = g_off[d + 1];
    int j = beg;
    for (; j + 4 <= end; j += 4) {
        int2 e0 = g_ent[j];
        int2 e1 = g_ent[j + 1];
        int2 e2 = g_ent[j + 2];
        int2 e3 = g_ent[j + 3];
        float k0 = __int_as_float(e0.y) * dd;
        float k1 = __int_as_float(e1.y) * dd;
        float k2 = __int_as_float(e2.y) * dd;
        float k3 = __int_as_float(e3.y) * dd;
        uint4 u0 = *((const uint4*)(g_HWp + (size_t)e0.x * 32) + q);
        uint4 u1 = *((const uint4*)(g_HWp + (size_t)e1.x * 32) + q);
        uint4 u2 = *((const uint4*)(g_HWp + (size_t)e2.x * 32) + q);
        uint4 u3 = *((const uint4*)(g_HWp + (size_t)e3.x * 32) + q);
#define GACC(U, K, A, B)                                                        \
        {                                                                       \
            float2 f0 = __half22float2(*reinterpret_cast<__half2*>(&U.x));      \
            float2 f1 = __half22float2(*reinterpret_cast<__half2*>(&U.y));      \
            float2 f2 = __half22float2(*reinterpret_cast<__half2*>(&U.z));      \
            float2 f3 = __half22float2(*reinterpret_cast<__half2*>(&U.w));      \
            A.x = fmaf(f0.x, K, A.x); A.y = fmaf(f0.y, K, A.y);                 \
            A.z = fmaf(f1.x, K, A.z); A.w = fmaf(f1.y, K, A.w);                 \
            B.x = fmaf(f2.x, K, B.x); B.y = fmaf(f2.y, K, B.y);                 \
            B.z = fmaf(f3.x, K, B.z); B.w = fmaf(f3.y, K, B.w);                 \
        }
        GACC(u0, k0, a0, b0)
        GACC(u1, k1, a1, b1r)
        GACC(u2, k2, a2, b2)
        GACC(u3, k3, a3, b3)
    }
    for (; j < end; j++) {
        int2 e0 = g_ent[j];
        float k0 = __int_as_float(e0.y) * dd;
        uint4 u0 = *((const uint4*)(g_HWp + (size_t)e0.x * 32) + q);
        GACC(u0, k0, a0, b0)
    }
#undef GACC
    float4 fa, fb;
    fa.x = (a0.x + a1.x) + (a2.x + a3.x);
    fa.y = (a0.y + a1.y) + (a2.y + a3.y);
    fa.z = (a0.z + a1.z) + (a2.z + a3.z);
    fa.w = (a0.w + a1.w) + (a2.w + a3.w);
    fb.x = (b0.x + b1r.x) + (b2.x + b3.x);
    fb.y = (b0.y + b1r.y) + (b2.y + b3.y);
    fb.z = (b0.z + b1r.z) + (b2.z + b3.z);
    fb.w = (b0.w + b1r.w) + (b2.w + b3.w);
    __half2 h0 = __floats2half2_rn(fa.x, fa.y);
    __half2 h1 = __floats2half2_rn(fa.z, fa.w);
    __half2 h2 = __floats2half2_rn(fb.x, fb.y);
    __half2 h3 = __floats2half2_rn(fb.z, fb.w);
    uint4 u;
    u.x = *reinterpret_cast<unsigned*>(&h0);
    u.y = *reinterpret_cast<unsigned*>(&h1);
    u.z = *reinterpret_cast<unsigned*>(&h2);
    u.w = *reinterpret_cast<unsigned*>(&h3);
    *((uint4*)(g_ACCh + (size_t)d * 32) + q) = u;
}

// ---------------- BN2 stats over fp16 ACC ----------------
__global__ __launch_bounds__(256) void k_stats2() {
    int t = threadIdx.x;
    float4 s4 = make_float4(0.f, 0.f, 0.f, 0.f);
    float4 q4 = make_float4(0.f, 0.f, 0.f, 0.f);
    const int total = NUN * 16;                 // uint2 units (4 cols each)
    int stride = gridDim.x * blockDim.x;
#pragma unroll 4
    for (int i = blockIdx.x * blockDim.x + t; i < total; i += stride) {
        uint2 u = ((const uint2*)g_ACCh)[i];
        float2 a = __half22float2(*reinterpret_cast<__half2*>(&u.x));
        float2 b = __half22float2(*reinterpret_cast<__half2*>(&u.y));
        s4.x += a.x; q4.x = fmaf(a.x, a.x, q4.x);
        s4.y += a.y; q4.y = fmaf(a.y, a.y, q4.y);
        s4.z += b.x; q4.z = fmaf(b.x, b.x, q4.z);
        s4.w += b.y; q4.w = fmaf(b.y, b.y, q4.w);
    }
    s4.x += __shfl_xor_sync(0xFFFFFFFFu, s4.x, 16);
    s4.y += __shfl_xor_sync(0xFFFFFFFFu, s4.y, 16);
    s4.z += __shfl_xor_sync(0xFFFFFFFFu, s4.z, 16);
    s4.w += __shfl_xor_sync(0xFFFFFFFFu, s4.w, 16);
    q4.x += __shfl_xor_sync(0xFFFFFFFFu, q4.x, 16);
    q4.y += __shfl_xor_sync(0xFFFFFFFFu, q4.y, 16);
    q4.z += __shfl_xor_sync(0xFFFFFFFFu, q4.z, 16);
    q4.w += __shfl_xor_sync(0xFFFFFFFFu, q4.w, 16);
    __shared__ float shs[8][64], shq[8][64];
    int wid = t >> 5, lane = t & 31;
    if (lane < 16) {
        shs[wid][lane * 4 + 0] = s4.x;
        shs[wid][lane * 4 + 1] = s4.y;
        shs[wid][lane * 4 + 2] = s4.z;
        shs[wid][lane * 4 + 3] = s4.w;
        shq[wid][lane * 4 + 0] = q4.x;
        shq[wid][lane * 4 + 1] = q4.y;
        shq[wid][lane * 4 + 2] = q4.z;
        shq[wid][lane * 4 + 3] = q4.w;
    }
    __syncthreads();
    if (t < 64) {
        float s = 0.f, qq = 0.f;
#pragma unroll
        for (int w = 0; w < 8; w++) { s += shs[w][t]; qq += shq[w][t]; }
        atomicAdd(&g_s2[t], (double)s);
        atomicAdd(&g_q2[t], (double)qq);
    }
}

// ---------------- finalize BN2 params ----------------
__global__ void k_meanvar2(const float* __restrict__ g, const float* __restrict__ b) {
    int t = threadIdx.x;
    if (t < CH) {
        double s = g_s2[t];
        double q = g_q2[t];
        double invN = 1.0 / (double)NUN;
        float mu = (float)(s * invN);
        float var = (float)(q * invN) - mu * mu;
        if (var < 0.f) var = 0.f;
        float rs = rsqrtf(var + EPSV);
        float sc = g[t] * rs;
        g_scale2[t] = sc;
        g_shift2[t] = b[t] - mu * sc;
    }
}

// ---------------- final: out = relu(bn2(ACCh)) ----------------
__global__ void k_final(float* __restrict__ out) {
    int i4 = blockIdx.x * blockDim.x + threadIdx.x;
    if (i4 < NUN * 16) {
        int c4 = i4 & 15;
        uint2 u = ((const uint2*)g_ACCh)[i4];
        float2 a = __half22float2(*reinterpret_cast<__half2*>(&u.x));
        float2 b = __half22float2(*reinterpret_cast<__half2*>(&u.y));
        float4 sc = ((const float4*)g_scale2)[c4];
        float4 sh = ((const float4*)g_shift2)[c4];
        float4 o;
        o.x = fmaxf(fmaf(a.x, sc.x, sh.x), 0.f);
        o.y = fmaxf(fmaf(a.y, sc.y, sh.y), 0.f);
        o.z = fmaxf(fmaf(b.x, sc.z, sh.z), 0.f);
        o.w = fmaxf(fmaf(b.y, sc.w, sh.w), 0.f);
        ((float4*)out)[i4] = o;
    }
}

// ---------------- optional tail ----------------
__global__ void k_tail(const int* __restrict__ ei, const int* __restrict__ batch,
                       float* __restrict__ out, int extra) {
    int i = blockIdx.x * blockDim.x + threadIdx.x;
    if (i < extra) {
        float v;
        if (i < 2 * NEDGE) v = (float)ei[i];
        else {
            int j = i - 2 * NEDGE;
            v = (j < NUN) ? (float)batch[j] : 0.f;
        }
        out[NUN * CH + i] = v;
    }
}

// ---------------- launch (round-11 topology + fast GEMMs) ----------------
extern "C" void kernel_launch(void* const* d_in, const int* in_sizes, int n_in,
                              void* d_out, int out_size) {
    const float* x       = (const float*)d_in[0];
    const int*   ei      = (const int*)  d_in[1];
    const int*   batch   = (const int*)  d_in[2];
    const int*   cluster = (const int*)  d_in[3];
    const float* score   = (const float*)d_in[4];
    const float* W1      = (const float*)d_in[5];
    const float* b1      = (const float*)d_in[6];
    const float* g1      = (const float*)d_in[7];
    const float* be1     = (const float*)d_in[8];
    const float* Wg      = (const float*)d_in[9];
    const float* bg      = (const float*)d_in[10];
    const float* g2      = (const float*)d_in[11];
    const float* be2     = (const float*)d_in[12];
    const int* srcA = ei;
    const int* dstA = ei + NEDGE;
    float* out = (float*)d_out;
    int extra = out_size - NUN * CH;

    static cudaStream_t sA = 0, sB = 0, sC = 0;
    static cudaEvent_t evRoot = 0, evA = 0, evB = 0, evC = 0;
    if (!sA) {
        cudaStreamCreateWithFlags(&sA, cudaStreamNonBlocking);
        cudaStreamCreateWithFlags(&sB, cudaStreamNonBlocking);
        cudaStreamCreateWithFlags(&sC, cudaStreamNonBlocking);
        cudaEventCreateWithFlags(&evRoot, cudaEventDisableTiming);
        cudaEventCreateWithFlags(&evA, cudaEventDisableTiming);
        cudaEventCreateWithFlags(&evB, cudaEventDisableTiming);
        cudaEventCreateWithFlags(&evC, cudaEventDisableTiming);
        cudaFuncSetAttribute(k_gemm1, cudaFuncAttributeMaxDynamicSharedMemorySize, GEMM_SMEM);
        cudaFuncSetAttribute(k_gemm2, cudaFuncAttributeMaxDynamicSharedMemorySize, GEMM_SMEM);
    }

    // ---- serial prologue on the captured stream ----
    k_init<<<(NUN + 255) / 256, 256>>>();                              // launch 0
    k_deg_hist<<<(NEDGE + 255) / 256, 256>>>(dstA, cluster);           // launch 1

    // ---- fork ----
    cudaEventRecord(evRoot, 0);
    cudaStreamWaitEvent(sA, evRoot, 0);
    cudaStreamWaitEvent(sB, evRoot, 0);

    // Chain A (scan + fill) on sA; Chain B (GEMMs) on sB.
    k_scanA<<<NSCAN, SCAN_BLK, 0, sA>>>();                             // launch 2
    k_gemm1<<<NB1, 256, GEMM_SMEM, sB>>>(x, W1, score, b1);            // launch 3 (ncu)
    k_scanB<<<1, 32, 0, sA>>>();                                       // launch 4
    k_scanC<<<NSCAN, SCAN_BLK, 0, sA>>>();                             // launch 5
    k_fill<<<(NEDGE + 255) / 256, 256, 0, sA>>>(srcA, dstA, cluster);  // launch 6
    k_bn1<<<1, 1024, 0, sB>>>(g1, be1);                                // launch 7
    k_gemm2<<<NB1, 256, GEMM_SMEM, sB>>>(Wg, score, b1);               // launch 8

    // Chain C: output tail passthrough
    if (extra > 0) {
        cudaStreamWaitEvent(sC, evRoot, 0);
        k_tail<<<(extra + 255) / 256, 256, 0, sC>>>(ei, batch, out, extra);
        cudaEventRecord(evC, sC);
    }

    // ---- join ----
    cudaEventRecord(evA, sA);
    cudaEventRecord(evB, sB);
    cudaStreamWaitEvent(0, evA, 0);
    cudaStreamWaitEvent(0, evB, 0);
    if (extra > 0) cudaStreamWaitEvent(0, evC, 0);

    // ---- serial epilogue on the captured stream ----
    k_gather<<<NUN / 32, 256>>>(cluster, bg);
    k_stats2<<<STATS_GRID, 256>>>();
    k_meanvar2<<<1, 64>>>(g2, be2);
    k_final<<<(NUN * 16 + 255) / 256, 256>>>(out);
}